// round 7
// baseline (speedup 1.0000x reference)
#include <cuda_runtime.h>
#include <math.h>
#include <stdint.h>

// hidden_states: [16, 13, 512, 768] fp32, reduce over axis=2 (512)
// out: [16, 13, 2304] = concat(sum, std(ddof=1), max).
//
// R7: TMA bulk pipeline + fused split-K fixup (no second kernel).
// CTA = (bl, 128-row chunk) -> 832 CTAs, one wave (6 CTA/SM, 36.9KB smem).
// Per-bl atomic counter; last CTA of each bl combines the 4 partials
// (L2-hot) and writes the final output, then resets the counter.

#define BL     208
#define SEQ    512
#define HID    768
#define RPC    128             // rows per CTA
#define NQ     (SEQ / RPC)     // 4
#define SROWS  4               // rows per stage
#define NST    3               // pipeline stages
#define NITER  (RPC / SROWS)   // 32
#define TPB    256
#define STAGE_BYTES (SROWS * HID * 4)   // 12288

__device__ float g_scratch[BL * NQ * 3 * HID];   // 7.3 MB
__device__ unsigned int g_count[BL];             // zero-init; reset each run

__device__ __forceinline__ uint32_t smem_u32(const void* p) {
    uint32_t a;
    asm("{ .reg .u64 t; cvta.to.shared.u64 t, %1; cvt.u32.u64 %0, t; }"
        : "=r"(a) : "l"(p));
    return a;
}
__device__ __forceinline__ void mbar_init(uint32_t bar, uint32_t cnt) {
    asm volatile("mbarrier.init.shared.b64 [%0], %1;" :: "r"(bar), "r"(cnt) : "memory");
}
__device__ __forceinline__ void mbar_arrive(uint32_t bar) {
    asm volatile("mbarrier.arrive.shared.b64 _, [%0];" :: "r"(bar) : "memory");
}
__device__ __forceinline__ void mbar_expect_tx(uint32_t bar, uint32_t tx) {
    asm volatile("mbarrier.arrive.expect_tx.shared.b64 _, [%0], %1;"
                 :: "r"(bar), "r"(tx) : "memory");
}
__device__ __forceinline__ void mbar_wait(uint32_t bar, uint32_t parity) {
    asm volatile(
        "{\n\t"
        ".reg .pred P;\n\t"
        "LAB_WAIT_%=:\n\t"
        "mbarrier.try_wait.parity.acquire.cta.shared::cta.b64 P, [%0], %1, 0x989680;\n\t"
        "@P bra.uni LAB_DONE_%=;\n\t"
        "bra.uni LAB_WAIT_%=;\n\t"
        "LAB_DONE_%=:\n\t"
        "}"
        :: "r"(bar), "r"(parity) : "memory");
}
__device__ __forceinline__ void bulk_ld(uint32_t dst_smem, const void* src,
                                        uint32_t bytes, uint32_t bar) {
    asm volatile(
        "cp.async.bulk.shared::cta.global.mbarrier::complete_tx::bytes "
        "[%0], [%1], %2, [%3];"
        :: "r"(dst_smem), "l"(src), "r"(bytes), "r"(bar) : "memory");
}

__global__ void __launch_bounds__(TPB) meanstdmax_kernel(
    const float* __restrict__ in, float* __restrict__ out)
{
    __shared__ __align__(128) float buf[NST][SROWS * HID];   // 36 KB
    __shared__ __align__(8) uint64_t full_bar[NST];
    __shared__ __align__(8) uint64_t empty_bar[NST];
    __shared__ unsigned int sh_islast;

    const int tid = threadIdx.x;
    const int bl  = blockIdx.x / NQ;
    const int q   = blockIdx.x % NQ;

    const float* base = in + (size_t)(bl * SEQ + q * RPC) * HID;

    uint32_t full_a  = smem_u32(&full_bar[0]);
    uint32_t empty_a = smem_u32(&empty_bar[0]);
    uint32_t buf_a[NST];
    #pragma unroll
    for (int s = 0; s < NST; s++) buf_a[s] = smem_u32(&buf[s][0]);

    if (tid == 0) {
        #pragma unroll
        for (int s = 0; s < NST; s++) {
            mbar_init(full_a  + s * 8, 1);
            mbar_init(empty_a + s * 8, TPB);
        }
    }
    __syncthreads();

    if (tid == 0) {
        #pragma unroll
        for (int s = 0; s < NST; s++) {
            mbar_expect_tx(full_a + s * 8, STAGE_BYTES);
            bulk_ld(buf_a[s], base + (size_t)s * SROWS * HID, STAGE_BYTES,
                    full_a + s * 8);
        }
    }

    float s0 = 0.f, s1 = 0.f, s2 = 0.f;
    float q0 = 0.f, q1 = 0.f, q2 = 0.f;
    float m0 = -INFINITY, m1 = -INFINITY, m2 = -INFINITY;

    for (int it = 0; it < NITER; it++) {
        const int st = it % NST;
        const uint32_t par = (uint32_t)(it / NST) & 1u;

        mbar_wait(full_a + st * 8, par);

        // float4 shared loads: thread t covers h = {4t..4t+3} mod pattern:
        // t -> float4 index t (h = 4t+0..3)? No: keep 3 scalar columns
        // replaced with float4 along row: 192 float4 per row, 256 threads.
        // Use 3 columns of float4 across rows instead: thread t handles
        // float4 cols t%192 on rows... simpler: stay with per-row float4:
        const float4* b4 = reinterpret_cast<const float4*>(&buf[st][0]);
        #pragma unroll
        for (int r = 0; r < SROWS; r += 4) {
            // 4 rows * 192 float4 = 768 float4; 256 threads * 3 each
            #pragma unroll
            for (int k = 0; k < 3; k++) {
                float4 v = b4[(r / 4) * 768 + k * 256 + tid];
                // accumulate into the lane-local stats; mapping of which h
                // each accumulator holds is irrelevant for sum/sumsq, but
                // NOT for per-h outputs -- so we must keep h-consistent
                // accumulators. k*256+tid selects a fixed (row, h4) pair
                // per k only if SROWS==4. With SROWS=4 the r-loop runs once,
                // so index = k*256+tid = row-major over 4 rows x 192 h4:
                // h4 = (k*256+tid) % 192 varies per k -- h-INCONSISTENT.
                // Therefore fold per-element into h-indexed accumulators
                // via scalar extraction below (see note): we instead
                // accumulate per (k) and fix h-mapping by re-gathering.
                (void)v;
            }
        }
        // NOTE: float4-over-rows breaks h-consistency; fall back to the
        // proven scalar-column pattern (crossbar is not the bottleneck).
        const float* b = &buf[st][0];
        #pragma unroll
        for (int r = 0; r < SROWS; r++) {
            float v0 = b[r * HID + tid];
            float v1 = b[r * HID + tid + 256];
            float v2 = b[r * HID + tid + 512];
            s0 += v0; q0 += v0 * v0; m0 = fmaxf(m0, v0);
            s1 += v1; q1 += v1 * v1; m1 = fmaxf(m1, v1);
            s2 += v2; q2 += v2 * v2; m2 = fmaxf(m2, v2);
        }

        mbar_arrive(empty_a + st * 8);

        if (tid == 0 && it + NST < NITER) {
            mbar_wait(empty_a + st * 8, par);
            mbar_expect_tx(full_a + st * 8, STAGE_BYTES);
            bulk_ld(buf_a[st], base + (size_t)(it + NST) * SROWS * HID,
                    STAGE_BYTES, full_a + st * 8);
        }
    }

    // write partials: scratch[bl][q][stat][h]
    float* scr = g_scratch + ((size_t)(bl * NQ + q) * 3) * HID;
    scr[tid]             = s0;  scr[tid + 256]           = s1;  scr[tid + 512]           = s2;
    scr[HID + tid]       = q0;  scr[HID + tid + 256]     = q1;  scr[HID + tid + 512]     = q2;
    scr[2 * HID + tid]   = m0;  scr[2 * HID + tid + 256] = m1;  scr[2 * HID + tid + 512] = m2;

    // split-K fixup: last CTA of this bl combines
    __threadfence();
    __syncthreads();
    if (tid == 0) sh_islast = (atomicAdd(&g_count[bl], 1u) == NQ - 1);
    __syncthreads();

    if (sh_islast) {
        __threadfence();   // acquire: order partial reads after the atomic
        #pragma unroll
        for (int k = 0; k < 3; k++) {
            const int h = tid + k * 256;
            float s = 0.f, sq = 0.f, mx = -INFINITY;
            #pragma unroll
            for (int qq = 0; qq < NQ; qq++) {
                const float* p = g_scratch + ((size_t)(bl * NQ + qq) * 3) * HID;
                s  += p[h];
                sq += p[HID + h];
                mx  = fmaxf(mx, p[2 * HID + h]);
            }
            const float mean = s * (1.0f / SEQ);
            const float var  = (sq - s * mean) * (1.0f / (SEQ - 1));
            const float sd   = sqrtf(fmaxf(var, 0.0f));

            float* o = out + (size_t)bl * (3 * HID);
            o[h]           = s;
            o[HID + h]     = sd;
            o[2 * HID + h] = mx;
        }
        if (tid == 0) g_count[bl] = 0;   // reset for next graph replay
    }
}

extern "C" void kernel_launch(void* const* d_in, const int* in_sizes, int n_in,
                              void* d_out, int out_size)
{
    const float* in = (const float*)d_in[0];
    float* out = (float*)d_out;

    meanstdmax_kernel<<<BL * NQ, TPB>>>(in, out);   // 832 CTAs, one wave
}